// round 11
// baseline (speedup 1.0000x reference)
#include <cuda_runtime.h>
#include <cuda_fp16.h>

// ---------------------------------------------------------------------------
// GCN forward, round 11 (= round 10 resubmitted after infra failure):
// round 9 baseline + ONE change: spmm 4-edge unroll (MLP 4 on gathers).
// ---------------------------------------------------------------------------

#define NMAXN 50000
#define EMAX  800000
#define FDIM  256
#define EPSV  1e-5f
#define RPW   10          // rows per warp in spmm_csr

__device__ __half g_hbuf[(size_t)NMAXN * FDIM];   // fp16 gemm output
__device__ float  g_buf1[(size_t)NMAXN * FDIM];   // fp32 spmm output
__device__ float  g_sum[FDIM];
__device__ float  g_sumsq[FDIM];
__device__ float  g_scale[FDIM];
__device__ float  g_shift[FDIM];

__device__ int   g_cnt[NMAXN];       // histogram (zero before & after each call)
__device__ int   g_cursor[NMAXN];
__device__ int   g_ptr[NMAXN + 1];
__device__ int   g_blk[64];
__device__ int   g_ccol[EMAX];
__device__ float g_cval[EMAX];

__device__ __forceinline__ unsigned f2tf(float f) {
    unsigned u;
    asm("cvt.rna.tf32.f32 %0, %1;" : "=r"(u) : "f"(f));
    return u;
}

// ---------------------------------------------------------------------------
// CSR build
// ---------------------------------------------------------------------------
__global__ void hist_kernel(const int* __restrict__ er, int E) {
    int e = blockIdx.x * blockDim.x + threadIdx.x;
    if (e < E) atomicAdd(&g_cnt[er[e]], 1);
}

// Block-local exclusive scan; also re-zeroes g_cnt for the next call.
__global__ __launch_bounds__(1024) void scan1_kernel(int n) {
    __shared__ int wsum[32];
    int tid = threadIdx.x;
    int i = blockIdx.x * 1024 + tid;
    int lane = tid & 31, wid = tid >> 5;
    int v = 0;
    if (i < n) {
        v = g_cnt[i];
        g_cnt[i] = 0;          // restore zero-invariant
    }
    int x = v;
    #pragma unroll
    for (int d = 1; d < 32; d <<= 1) {
        int t = __shfl_up_sync(0xffffffffu, x, d);
        if (lane >= d) x += t;
    }
    if (lane == 31) wsum[wid] = x;
    __syncthreads();
    if (wid == 0) {
        int y = wsum[lane];
        #pragma unroll
        for (int d = 1; d < 32; d <<= 1) {
            int t = __shfl_up_sync(0xffffffffu, y, d);
            if (lane >= d) y += t;
        }
        wsum[lane] = y;
    }
    __syncthreads();
    int incl = x + (wid > 0 ? wsum[wid - 1] : 0);
    if (i < n) g_ptr[i] = incl - v;
    if (tid == 1023) g_blk[blockIdx.x] = incl;
}

// shuffle-scan of <=64 block totals (2 warps + cross-warp fixup)
__global__ void scan2_kernel(int nb) {
    __shared__ int w0_total;
    int tid = threadIdx.x;            // 64 threads
    int lane = tid & 31, wid = tid >> 5;
    int v = (tid < nb) ? g_blk[tid] : 0;
    int x = v;
    #pragma unroll
    for (int d = 1; d < 32; d <<= 1) {
        int t = __shfl_up_sync(0xffffffffu, x, d);
        if (lane >= d) x += t;
    }
    if (wid == 0 && lane == 31) w0_total = x;
    __syncthreads();
    int excl = x - v + (wid == 1 ? w0_total : 0);
    if (tid < nb) g_blk[tid] = excl;
}

__global__ __launch_bounds__(1024) void scan3_kernel(int n, int E) {
    int i = blockIdx.x * 1024 + threadIdx.x;
    if (i < n) {
        int p = g_ptr[i] + g_blk[i >> 10];
        g_ptr[i] = p;
        g_cursor[i] = p;
    }
    if (i == 0) g_ptr[n] = E;
    if (i < FDIM) { g_sum[i] = 0.f; g_sumsq[i] = 0.f; }
}

__global__ void scatter_kernel(const int* __restrict__ er, const int* __restrict__ ec,
                               const float* __restrict__ ev, int E) {
    int e = blockIdx.x * blockDim.x + threadIdx.x;
    if (e >= E) return;
    int pos = atomicAdd(&g_cursor[er[e]], 1);
    g_ccol[pos] = ec[e];
    g_cval[pos] = ev[e];
}

// ---------------------------------------------------------------------------
// CSR SpMM (fp16 gather -> fp32 accum/output) with fused BN statistics.
// 4-edge unroll: 4 independent uint4 gathers in flight per lane (MLP 4).
// ---------------------------------------------------------------------------
__global__ __launch_bounds__(256) void spmm_csr(
    const uint4* __restrict__ x, float4* __restrict__ out, int N)
{
    __shared__ __align__(16) float4 sm_s[8][64];
    __shared__ __align__(16) float4 sm_q[8][64];

    int lane = threadIdx.x & 31;
    int w = threadIdx.x >> 5;
    int r0 = (blockIdx.x * 8 + w) * RPW;

    float s[8] = {}, q[8] = {};

    int rend = min(r0 + RPW, N);
    for (int r = r0; r < rend; r++) {
        int e = __ldg(&g_ptr[r]);
        int end = __ldg(&g_ptr[r + 1]);
        float a[8] = {};
        for (; e + 3 < end; e += 4) {
            int   c0 = __ldg(&g_ccol[e]),     c1 = __ldg(&g_ccol[e + 1]);
            int   c2 = __ldg(&g_ccol[e + 2]), c3 = __ldg(&g_ccol[e + 3]);
            float w0 = __ldg(&g_cval[e]),     w1 = __ldg(&g_cval[e + 1]);
            float w2 = __ldg(&g_cval[e + 2]), w3 = __ldg(&g_cval[e + 3]);
            uint4 u0 = __ldg(x + (size_t)c0 * 32 + lane);
            uint4 u1 = __ldg(x + (size_t)c1 * 32 + lane);
            uint4 u2 = __ldg(x + (size_t)c2 * 32 + lane);
            uint4 u3 = __ldg(x + (size_t)c3 * 32 + lane);
            const unsigned* p0 = &u0.x;
            const unsigned* p1 = &u1.x;
            const unsigned* p2 = &u2.x;
            const unsigned* p3 = &u3.x;
            #pragma unroll
            for (int j = 0; j < 4; j++) {
                float2 f0 = __half22float2(*reinterpret_cast<const __half2*>(&p0[j]));
                float2 f1 = __half22float2(*reinterpret_cast<const __half2*>(&p1[j]));
                float2 f2 = __half22float2(*reinterpret_cast<const __half2*>(&p2[j]));
                float2 f3 = __half22float2(*reinterpret_cast<const __half2*>(&p3[j]));
                a[j*2+0] = fmaf(w0, f0.x, fmaf(w1, f1.x, fmaf(w2, f2.x, fmaf(w3, f3.x, a[j*2+0]))));
                a[j*2+1] = fmaf(w0, f0.y, fmaf(w1, f1.y, fmaf(w2, f2.y, fmaf(w3, f3.y, a[j*2+1]))));
            }
        }
        for (; e < end; e++) {
            int   c0 = __ldg(&g_ccol[e]);
            float w0 = __ldg(&g_cval[e]);
            uint4 u = __ldg(x + (size_t)c0 * 32 + lane);
            const unsigned* up = &u.x;
            #pragma unroll
            for (int j = 0; j < 4; j++) {
                float2 fu = __half22float2(*reinterpret_cast<const __half2*>(&up[j]));
                a[j*2+0] = fmaf(w0, fu.x, a[j*2+0]);
                a[j*2+1] = fmaf(w0, fu.y, a[j*2+1]);
            }
        }
        out[(size_t)r * 64 + lane * 2]     = make_float4(a[0], a[1], a[2], a[3]);
        out[(size_t)r * 64 + lane * 2 + 1] = make_float4(a[4], a[5], a[6], a[7]);
        #pragma unroll
        for (int j = 0; j < 8; j++) {
            s[j] += a[j];
            q[j] = fmaf(a[j], a[j], q[j]);
        }
    }

    sm_s[w][lane * 2]     = make_float4(s[0], s[1], s[2], s[3]);
    sm_s[w][lane * 2 + 1] = make_float4(s[4], s[5], s[6], s[7]);
    sm_q[w][lane * 2]     = make_float4(q[0], q[1], q[2], q[3]);
    sm_q[w][lane * 2 + 1] = make_float4(q[4], q[5], q[6], q[7]);
    __syncthreads();

    int t = threadIdx.x;
    if (t < 64) {
        float4 acc = sm_s[0][t];
        #pragma unroll
        for (int ww = 1; ww < 8; ww++) {
            float4 v = sm_s[ww][t];
            acc.x += v.x; acc.y += v.y; acc.z += v.z; acc.w += v.w;
        }
        int c = t * 4;
        atomicAdd(&g_sum[c + 0], acc.x); atomicAdd(&g_sum[c + 1], acc.y);
        atomicAdd(&g_sum[c + 2], acc.z); atomicAdd(&g_sum[c + 3], acc.w);
    } else if (t < 128) {
        int sl = t - 64;
        float4 acc = sm_q[0][sl];
        #pragma unroll
        for (int ww = 1; ww < 8; ww++) {
            float4 v = sm_q[ww][sl];
            acc.x += v.x; acc.y += v.y; acc.z += v.z; acc.w += v.w;
        }
        int c = sl * 4;
        atomicAdd(&g_sumsq[c + 0], acc.x); atomicAdd(&g_sumsq[c + 1], acc.y);
        atomicAdd(&g_sumsq[c + 2], acc.z); atomicAdd(&g_sumsq[c + 3], acc.w);
    }
}

__global__ void finalize_kernel(const float* __restrict__ gamma,
                                const float* __restrict__ beta, float invN) {
    int c = threadIdx.x;
    float m = g_sum[c] * invN;
    float var = g_sumsq[c] * invN - m * m;
    float rs = rsqrtf(var + EPSV);
    float sc = rs * gamma[c];
    g_scale[c] = sc;
    g_shift[c] = beta[c] - m * sc;
    g_sum[c] = 0.f;
    g_sumsq[c] = 0.f;
}

// ---------------------------------------------------------------------------
// Software-pipelined tf32 GEMM: C = op(A) @ B (+ bias).
// Output: fp16 (Ch != null) for spmm consumers, else fp32 (C).
// ---------------------------------------------------------------------------
__global__ __launch_bounds__(256) void gemm_tf32(
    const float* __restrict__ A, const float* __restrict__ B,
    const float* __restrict__ bias, const int* __restrict__ gather,
    int use_bn, float* __restrict__ C, __half* __restrict__ Ch,
    int M, int Ncols, int K)
{
    __shared__ __align__(16) float As[128 * 36];
    __shared__ __align__(16) float Bs[32 * 72];

    int tid = threadIdx.x;
    int lane = tid & 31, w = tid >> 5;
    int wm = w >> 1, wn = w & 1;
    int g = lane >> 2, tg = lane & 3;
    int row0 = blockIdx.y * 128, col0 = blockIdx.x * 64;

    float acc[2][4][4];
    #pragma unroll
    for (int mi = 0; mi < 2; mi++)
        #pragma unroll
        for (int ni = 0; ni < 4; ni++)
            #pragma unroll
            for (int j = 0; j < 4; j++) acc[mi][ni][j] = 0.f;

    int asrc[4];
    #pragma unroll
    for (int p = 0; p < 4; p++) {
        int idx = tid + p * 256;
        int grow = row0 + (idx >> 3);
        int sr = grow < M ? grow : M - 1;
        if (gather) sr = __ldg(gather + sr);
        asrc[p] = sr;
    }

    float4 ra[4], rb[2];
    #pragma unroll
    for (int p = 0; p < 4; p++) {
        int idx = tid + p * 256;
        ra[p] = *reinterpret_cast<const float4*>(A + (size_t)asrc[p] * K + (idx & 7) * 4);
    }
    #pragma unroll
    for (int p = 0; p < 2; p++) {
        int idx = tid + p * 256;
        rb[p] = *reinterpret_cast<const float4*>(
            B + (size_t)(idx >> 4) * Ncols + col0 + (idx & 15) * 4);
    }

    for (int kt = 0; kt < K; kt += 32) {
        #pragma unroll
        for (int p = 0; p < 4; p++) {
            int idx = tid + p * 256;
            int row = idx >> 3, c4 = idx & 7;
            int cb = kt + c4 * 4;
            float4 v = ra[p];
            if (use_bn) {
                v.x = fmaxf(fmaf(v.x, g_scale[cb + 0], g_shift[cb + 0]), 0.f);
                v.y = fmaxf(fmaf(v.y, g_scale[cb + 1], g_shift[cb + 1]), 0.f);
                v.z = fmaxf(fmaf(v.z, g_scale[cb + 2], g_shift[cb + 2]), 0.f);
                v.w = fmaxf(fmaf(v.w, g_scale[cb + 3], g_shift[cb + 3]), 0.f);
            }
            float4 o;
            o.x = __uint_as_float(f2tf(v.x));
            o.y = __uint_as_float(f2tf(v.y));
            o.z = __uint_as_float(f2tf(v.z));
            o.w = __uint_as_float(f2tf(v.w));
            *reinterpret_cast<float4*>(As + row * 36 + c4 * 4) = o;
        }
        #pragma unroll
        for (int p = 0; p < 2; p++) {
            int idx = tid + p * 256;
            int row = idx >> 4, c4 = idx & 15;
            float4 v = rb[p];
            float4 o;
            o.x = __uint_as_float(f2tf(v.x));
            o.y = __uint_as_float(f2tf(v.y));
            o.z = __uint_as_float(f2tf(v.z));
            o.w = __uint_as_float(f2tf(v.w));
            *reinterpret_cast<float4*>(Bs + row * 72 + c4 * 4) = o;
        }
        __syncthreads();

        int ktn = kt + 32;
        if (ktn < K) {
            #pragma unroll
            for (int p = 0; p < 4; p++) {
                int idx = tid + p * 256;
                ra[p] = *reinterpret_cast<const float4*>(
                    A + (size_t)asrc[p] * K + ktn + (idx & 7) * 4);
            }
            #pragma unroll
            for (int p = 0; p < 2; p++) {
                int idx = tid + p * 256;
                rb[p] = *reinterpret_cast<const float4*>(
                    B + (size_t)(ktn + (idx >> 4)) * Ncols + col0 + (idx & 15) * 4);
            }
        }

        #pragma unroll
        for (int kk = 0; kk < 4; kk++) {
            unsigned a[2][4], b[4][2];
            #pragma unroll
            for (int mi = 0; mi < 2; mi++) {
                int rb_ = wm * 32 + mi * 16;
                int kc = kk * 8 + tg;
                a[mi][0] = __float_as_uint(As[(rb_ + g)     * 36 + kc]);
                a[mi][1] = __float_as_uint(As[(rb_ + g + 8) * 36 + kc]);
                a[mi][2] = __float_as_uint(As[(rb_ + g)     * 36 + kc + 4]);
                a[mi][3] = __float_as_uint(As[(rb_ + g + 8) * 36 + kc + 4]);
            }
            #pragma unroll
            for (int ni = 0; ni < 4; ni++) {
                int col = wn * 32 + ni * 8 + g;
                b[ni][0] = __float_as_uint(Bs[(kk * 8 + tg)     * 72 + col]);
                b[ni][1] = __float_as_uint(Bs[(kk * 8 + tg + 4) * 72 + col]);
            }
            #pragma unroll
            for (int mi = 0; mi < 2; mi++)
                #pragma unroll
                for (int ni = 0; ni < 4; ni++)
                    asm volatile(
                        "mma.sync.aligned.m16n8k8.row.col.f32.tf32.tf32.f32 "
                        "{%0,%1,%2,%3}, {%4,%5,%6,%7}, {%8,%9}, {%0,%1,%2,%3};"
                        : "+f"(acc[mi][ni][0]), "+f"(acc[mi][ni][1]),
                          "+f"(acc[mi][ni][2]), "+f"(acc[mi][ni][3])
                        : "r"(a[mi][0]), "r"(a[mi][1]), "r"(a[mi][2]), "r"(a[mi][3]),
                          "r"(b[ni][0]), "r"(b[ni][1]));
        }
        __syncthreads();
    }

    #pragma unroll
    for (int mi = 0; mi < 2; mi++) {
        int r = row0 + wm * 32 + mi * 16 + g;
        #pragma unroll
        for (int ni = 0; ni < 4; ni++) {
            int c = col0 + wn * 32 + ni * 8 + tg * 2;
            float bx = bias ? __ldg(bias + c) : 0.f;
            float by = bias ? __ldg(bias + c + 1) : 0.f;
            float v0 = acc[mi][ni][0] + bx, v1 = acc[mi][ni][1] + by;
            float v2 = acc[mi][ni][2] + bx, v3 = acc[mi][ni][3] + by;
            if (Ch) {
                if (r < M)
                    *reinterpret_cast<__half2*>(Ch + (size_t)r * Ncols + c) =
                        __floats2half2_rn(v0, v1);
                if (r + 8 < M)
                    *reinterpret_cast<__half2*>(Ch + (size_t)(r + 8) * Ncols + c) =
                        __floats2half2_rn(v2, v3);
            } else {
                if (r < M)
                    *reinterpret_cast<float2*>(C + (size_t)r * Ncols + c) =
                        make_float2(v0, v1);
                if (r + 8 < M)
                    *reinterpret_cast<float2*>(C + (size_t)(r + 8) * Ncols + c) =
                        make_float2(v2, v3);
            }
        }
    }
}

// ---------------------------------------------------------------------------
// Launch sequence (single stream, graph-capturable: kernels only).
// ---------------------------------------------------------------------------
extern "C" void kernel_launch(void* const* d_in, const int* in_sizes, int n_in,
                              void* d_out, int out_size) {
    const float* features  = (const float*)d_in[0];
    const float* edge_vals = (const float*)d_in[1];
    const float* W1  = (const float*)d_in[2];
    const float* db1 = (const float*)d_in[3];
    // d_in[4] = b1  : cancels in BatchNorm
    const float* g1  = (const float*)d_in[5];
    const float* be1 = (const float*)d_in[6];
    const float* W2  = (const float*)d_in[7];
    // d_in[8] = b2  : cancels in BatchNorm
    const float* g2  = (const float*)d_in[9];
    const float* be2 = (const float*)d_in[10];
    const float* Wf  = (const float*)d_in[11];
    const float* bf  = (const float*)d_in[12];
    const int* erows = (const int*)d_in[13];
    const int* ecols = (const int*)d_in[14];
    const int* idx   = (const int*)d_in[15];
    float* out = (float*)d_out;

    int N = in_sizes[0] / FDIM;   // 50000
    int E = in_sizes[1];          // 800000
    int M = in_sizes[15];         // 25000
    float invN = 1.0f / (float)N;

    float *b1;
    __half *hb;
    cudaGetSymbolAddress((void**)&b1, g_buf1);
    cudaGetSymbolAddress((void**)&hb, g_hbuf);

    int eblocks = (E + 255) / 256;
    int nb = (N + 1023) / 1024;
    dim3 ggrid(FDIM / 64, (N + 127) / 128);
    int spmm_blocks = (N + 8 * RPW - 1) / (8 * RPW);

    // CSR build (g_cnt is zero on entry; scan1 restores the invariant)
    hist_kernel<<<eblocks, 256>>>(erows, E);
    scan1_kernel<<<nb, 1024>>>(N);
    scan2_kernel<<<1, 64>>>(nb);
    scan3_kernel<<<nb, 1024>>>(N, E);
    scatter_kernel<<<eblocks, 256>>>(erows, ecols, edge_vals, E);

    // layer 1 (gemm -> fp16, spmm fp16->fp32 + stats)
    gemm_tf32<<<ggrid, 256>>>(features, W1, db1, nullptr, 0, nullptr, hb, N, FDIM, FDIM);
    spmm_csr<<<spmm_blocks, 256>>>((const uint4*)hb, (float4*)b1, N);
    finalize_kernel<<<1, 256>>>(g1, be1, invN);

    // layer 2 (BN1+ReLU fused into A-load; gemm -> fp16)
    gemm_tf32<<<ggrid, 256>>>(b1, W2, nullptr, nullptr, 1, nullptr, hb, N, FDIM, FDIM);
    spmm_csr<<<spmm_blocks, 256>>>((const uint4*)hb, (float4*)b1, N);
    finalize_kernel<<<1, 256>>>(g2, be2, invN);

    // head (BN2+ReLU + gather fused into A-load; fp32 out)
    gemm_tf32<<<dim3(128 / 64, (M + 127) / 128), 256>>>(
        b1, Wf, bf, idx, 1, out, nullptr, M, 128, FDIM);
}

// round 12
// speedup vs baseline: 1.0496x; 1.0496x over previous
#include <cuda_runtime.h>
#include <cuda_fp16.h>

// ---------------------------------------------------------------------------
// GCN forward, round 12 (base = round 9 best @327.8us):
//   - spmm: reverted to round-9 2-edge form (4-edge unroll convicted: +12.7us)
//   - finalize kernels removed: per-layer stat buffers; consumer GEMM computes
//     BN scale/shift inline into smem (also removes g_scale/g_shift L2 reads)
//   - scan2 removed: scan3 blocks redundantly reduce their block-offset
//   Launches: 12 -> 9.
// ---------------------------------------------------------------------------

#define NMAXN 50000
#define EMAX  800000
#define FDIM  256
#define EPSV  1e-5f
#define RPW   10          // rows per warp in spmm_csr

__device__ __half g_hbuf[(size_t)NMAXN * FDIM];   // fp16 gemm output
__device__ float  g_buf1[(size_t)NMAXN * FDIM];   // fp32 spmm output
__device__ float  g_sum1[FDIM];
__device__ float  g_sumsq1[FDIM];
__device__ float  g_sum2[FDIM];
__device__ float  g_sumsq2[FDIM];

__device__ int   g_cnt[NMAXN];       // histogram (zero before & after each call)
__device__ int   g_cursor[NMAXN];
__device__ int   g_ptr[NMAXN + 1];
__device__ int   g_blk[64];          // scan1 block totals (read-only after scan1)
__device__ int   g_ccol[EMAX];
__device__ float g_cval[EMAX];

__device__ __forceinline__ unsigned f2tf(float f) {
    unsigned u;
    asm("cvt.rna.tf32.f32 %0, %1;" : "=r"(u) : "f"(f));
    return u;
}

// ---------------------------------------------------------------------------
// CSR build
// ---------------------------------------------------------------------------
__global__ void hist_kernel(const int* __restrict__ er, int E) {
    int e = blockIdx.x * blockDim.x + threadIdx.x;
    if (e < E) atomicAdd(&g_cnt[er[e]], 1);
}

// Block-local exclusive scan; also re-zeroes g_cnt for the next call.
__global__ __launch_bounds__(1024) void scan1_kernel(int n) {
    __shared__ int wsum[32];
    int tid = threadIdx.x;
    int i = blockIdx.x * 1024 + tid;
    int lane = tid & 31, wid = tid >> 5;
    int v = 0;
    if (i < n) {
        v = g_cnt[i];
        g_cnt[i] = 0;          // restore zero-invariant
    }
    int x = v;
    #pragma unroll
    for (int d = 1; d < 32; d <<= 1) {
        int t = __shfl_up_sync(0xffffffffu, x, d);
        if (lane >= d) x += t;
    }
    if (lane == 31) wsum[wid] = x;
    __syncthreads();
    if (wid == 0) {
        int y = wsum[lane];
        #pragma unroll
        for (int d = 1; d < 32; d <<= 1) {
            int t = __shfl_up_sync(0xffffffffu, y, d);
            if (lane >= d) y += t;
        }
        wsum[lane] = y;
    }
    __syncthreads();
    int incl = x + (wid > 0 ? wsum[wid - 1] : 0);
    if (i < n) g_ptr[i] = incl - v;
    if (tid == 1023) g_blk[blockIdx.x] = incl;
}

// Add block offsets (each block redundantly reduces g_blk[0..bid-1]),
// write cursors, finish ptr[n], zero both layers' BN stat accumulators.
__global__ __launch_bounds__(1024) void scan3_kernel(int n, int E) {
    __shared__ int soff[2];
    int tid = threadIdx.x;
    // 64-thread reduction of g_blk[t] for t < blockIdx.x
    if (tid < 64) {
        int v = (tid < blockIdx.x) ? g_blk[tid] : 0;
        #pragma unroll
        for (int d = 16; d > 0; d >>= 1)
            v += __shfl_down_sync(0xffffffffu, v, d);
        if ((tid & 31) == 0) soff[tid >> 5] = v;
    }
    __syncthreads();
    int off = soff[0] + soff[1];
    int i = blockIdx.x * 1024 + tid;
    if (i < n) {
        int p = g_ptr[i] + off;
        g_ptr[i] = p;
        g_cursor[i] = p;
    }
    if (i == 0) g_ptr[n] = E;
    if (i < FDIM) {
        g_sum1[i] = 0.f; g_sumsq1[i] = 0.f;
        g_sum2[i] = 0.f; g_sumsq2[i] = 0.f;
    }
}

__global__ void scatter_kernel(const int* __restrict__ er, const int* __restrict__ ec,
                               const float* __restrict__ ev, int E) {
    int e = blockIdx.x * blockDim.x + threadIdx.x;
    if (e >= E) return;
    int pos = atomicAdd(&g_cursor[er[e]], 1);
    g_ccol[pos] = ec[e];
    g_cval[pos] = ev[e];
}

// ---------------------------------------------------------------------------
// CSR SpMM (fp16 gather -> fp32 accum/output) with fused BN statistics.
// Round-9 2-edge form; stats go into the given per-layer buffers.
// ---------------------------------------------------------------------------
__global__ __launch_bounds__(256) void spmm_csr(
    const uint4* __restrict__ x, float4* __restrict__ out,
    float* __restrict__ sumbuf, float* __restrict__ sqbuf, int N)
{
    __shared__ __align__(16) float4 sm_s[8][64];
    __shared__ __align__(16) float4 sm_q[8][64];

    int lane = threadIdx.x & 31;
    int w = threadIdx.x >> 5;
    int r0 = (blockIdx.x * 8 + w) * RPW;

    float s[8] = {}, q[8] = {};

    int rend = min(r0 + RPW, N);
    for (int r = r0; r < rend; r++) {
        int e = __ldg(&g_ptr[r]);
        int end = __ldg(&g_ptr[r + 1]);
        float a[8] = {};
        for (; e + 1 < end; e += 2) {
            int   c0 = __ldg(&g_ccol[e]),  c1 = __ldg(&g_ccol[e + 1]);
            float w0 = __ldg(&g_cval[e]),  w1 = __ldg(&g_cval[e + 1]);
            uint4 u = __ldg(x + (size_t)c0 * 32 + lane);
            uint4 v = __ldg(x + (size_t)c1 * 32 + lane);
            const unsigned* up = &u.x;
            const unsigned* vp = &v.x;
            #pragma unroll
            for (int j = 0; j < 4; j++) {
                float2 fu = __half22float2(*reinterpret_cast<const __half2*>(&up[j]));
                float2 fv = __half22float2(*reinterpret_cast<const __half2*>(&vp[j]));
                a[j * 2 + 0] = fmaf(w0, fu.x, fmaf(w1, fv.x, a[j * 2 + 0]));
                a[j * 2 + 1] = fmaf(w0, fu.y, fmaf(w1, fv.y, a[j * 2 + 1]));
            }
        }
        if (e < end) {
            int   c0 = __ldg(&g_ccol[e]);
            float w0 = __ldg(&g_cval[e]);
            uint4 u = __ldg(x + (size_t)c0 * 32 + lane);
            const unsigned* up = &u.x;
            #pragma unroll
            for (int j = 0; j < 4; j++) {
                float2 fu = __half22float2(*reinterpret_cast<const __half2*>(&up[j]));
                a[j * 2 + 0] = fmaf(w0, fu.x, a[j * 2 + 0]);
                a[j * 2 + 1] = fmaf(w0, fu.y, a[j * 2 + 1]);
            }
        }
        out[(size_t)r * 64 + lane * 2]     = make_float4(a[0], a[1], a[2], a[3]);
        out[(size_t)r * 64 + lane * 2 + 1] = make_float4(a[4], a[5], a[6], a[7]);
        #pragma unroll
        for (int j = 0; j < 8; j++) {
            s[j] += a[j];
            q[j] = fmaf(a[j], a[j], q[j]);
        }
    }

    sm_s[w][lane * 2]     = make_float4(s[0], s[1], s[2], s[3]);
    sm_s[w][lane * 2 + 1] = make_float4(s[4], s[5], s[6], s[7]);
    sm_q[w][lane * 2]     = make_float4(q[0], q[1], q[2], q[3]);
    sm_q[w][lane * 2 + 1] = make_float4(q[4], q[5], q[6], q[7]);
    __syncthreads();

    int t = threadIdx.x;
    if (t < 64) {
        float4 acc = sm_s[0][t];
        #pragma unroll
        for (int ww = 1; ww < 8; ww++) {
            float4 v = sm_s[ww][t];
            acc.x += v.x; acc.y += v.y; acc.z += v.z; acc.w += v.w;
        }
        int c = t * 4;
        atomicAdd(&sumbuf[c + 0], acc.x); atomicAdd(&sumbuf[c + 1], acc.y);
        atomicAdd(&sumbuf[c + 2], acc.z); atomicAdd(&sumbuf[c + 3], acc.w);
    } else if (t < 128) {
        int sl = t - 64;
        float4 acc = sm_q[0][sl];
        #pragma unroll
        for (int ww = 1; ww < 8; ww++) {
            float4 v = sm_q[ww][sl];
            acc.x += v.x; acc.y += v.y; acc.z += v.z; acc.w += v.w;
        }
        int c = sl * 4;
        atomicAdd(&sqbuf[c + 0], acc.x); atomicAdd(&sqbuf[c + 1], acc.y);
        atomicAdd(&sqbuf[c + 2], acc.z); atomicAdd(&sqbuf[c + 3], acc.w);
    }
}

// ---------------------------------------------------------------------------
// Software-pipelined tf32 GEMM: C = op(A) @ B (+ bias).
// If bn_gamma != null: BN scale/shift computed inline (from sum/sq buffers)
// into smem at kernel start; A-loads apply relu(x*scale+shift).
// Output: fp16 (Ch != null) for spmm consumers, else fp32 (C).
// ---------------------------------------------------------------------------
__global__ __launch_bounds__(256) void gemm_tf32(
    const float* __restrict__ A, const float* __restrict__ B,
    const float* __restrict__ bias, const int* __restrict__ gather,
    const float* __restrict__ bn_sum, const float* __restrict__ bn_sq,
    const float* __restrict__ bn_gamma, const float* __restrict__ bn_beta,
    float invN, float* __restrict__ C, __half* __restrict__ Ch,
    int M, int Ncols, int K)
{
    __shared__ __align__(16) float As[128 * 36];
    __shared__ __align__(16) float Bs[32 * 72];
    __shared__ float s_scale[FDIM];
    __shared__ float s_shift[FDIM];

    int tid = threadIdx.x;
    int lane = tid & 31, w = tid >> 5;
    int wm = w >> 1, wn = w & 1;
    int g = lane >> 2, tg = lane & 3;
    int row0 = blockIdx.y * 128, col0 = blockIdx.x * 64;

    // Inline BN finalize: 256 threads cover FDIM columns exactly.
    if (bn_gamma) {
        float m = bn_sum[tid] * invN;
        float var = bn_sq[tid] * invN - m * m;
        float sc = rsqrtf(var + EPSV) * bn_gamma[tid];
        s_scale[tid] = sc;
        s_shift[tid] = bn_beta[tid] - m * sc;
    }
    __syncthreads();

    float acc[2][4][4];
    #pragma unroll
    for (int mi = 0; mi < 2; mi++)
        #pragma unroll
        for (int ni = 0; ni < 4; ni++)
            #pragma unroll
            for (int j = 0; j < 4; j++) acc[mi][ni][j] = 0.f;

    int asrc[4];
    #pragma unroll
    for (int p = 0; p < 4; p++) {
        int idx = tid + p * 256;
        int grow = row0 + (idx >> 3);
        int sr = grow < M ? grow : M - 1;
        if (gather) sr = __ldg(gather + sr);
        asrc[p] = sr;
    }

    float4 ra[4], rb[2];
    #pragma unroll
    for (int p = 0; p < 4; p++) {
        int idx = tid + p * 256;
        ra[p] = *reinterpret_cast<const float4*>(A + (size_t)asrc[p] * K + (idx & 7) * 4);
    }
    #pragma unroll
    for (int p = 0; p < 2; p++) {
        int idx = tid + p * 256;
        rb[p] = *reinterpret_cast<const float4*>(
            B + (size_t)(idx >> 4) * Ncols + col0 + (idx & 15) * 4);
    }

    for (int kt = 0; kt < K; kt += 32) {
        #pragma unroll
        for (int p = 0; p < 4; p++) {
            int idx = tid + p * 256;
            int row = idx >> 3, c4 = idx & 7;
            int cb = kt + c4 * 4;
            float4 v = ra[p];
            if (bn_gamma) {
                v.x = fmaxf(fmaf(v.x, s_scale[cb + 0], s_shift[cb + 0]), 0.f);
                v.y = fmaxf(fmaf(v.y, s_scale[cb + 1], s_shift[cb + 1]), 0.f);
                v.z = fmaxf(fmaf(v.z, s_scale[cb + 2], s_shift[cb + 2]), 0.f);
                v.w = fmaxf(fmaf(v.w, s_scale[cb + 3], s_shift[cb + 3]), 0.f);
            }
            float4 o;
            o.x = __uint_as_float(f2tf(v.x));
            o.y = __uint_as_float(f2tf(v.y));
            o.z = __uint_as_float(f2tf(v.z));
            o.w = __uint_as_float(f2tf(v.w));
            *reinterpret_cast<float4*>(As + row * 36 + c4 * 4) = o;
        }
        #pragma unroll
        for (int p = 0; p < 2; p++) {
            int idx = tid + p * 256;
            int row = idx >> 4, c4 = idx & 15;
            float4 v = rb[p];
            float4 o;
            o.x = __uint_as_float(f2tf(v.x));
            o.y = __uint_as_float(f2tf(v.y));
            o.z = __uint_as_float(f2tf(v.z));
            o.w = __uint_as_float(f2tf(v.w));
            *reinterpret_cast<float4*>(Bs + row * 72 + c4 * 4) = o;
        }
        __syncthreads();

        int ktn = kt + 32;
        if (ktn < K) {
            #pragma unroll
            for (int p = 0; p < 4; p++) {
                int idx = tid + p * 256;
                ra[p] = *reinterpret_cast<const float4*>(
                    A + (size_t)asrc[p] * K + ktn + (idx & 7) * 4);
            }
            #pragma unroll
            for (int p = 0; p < 2; p++) {
                int idx = tid + p * 256;
                rb[p] = *reinterpret_cast<const float4*>(
                    B + (size_t)(ktn + (idx >> 4)) * Ncols + col0 + (idx & 15) * 4);
            }
        }

        #pragma unroll
        for (int kk = 0; kk < 4; kk++) {
            unsigned a[2][4], b[4][2];
            #pragma unroll
            for (int mi = 0; mi < 2; mi++) {
                int rb_ = wm * 32 + mi * 16;
                int kc = kk * 8 + tg;
                a[mi][0] = __float_as_uint(As[(rb_ + g)     * 36 + kc]);
                a[mi][1] = __float_as_uint(As[(rb_ + g + 8) * 36 + kc]);
                a[mi][2] = __float_as_uint(As[(rb_ + g)     * 36 + kc + 4]);
                a[mi][3] = __float_as_uint(As[(rb_ + g + 8) * 36 + kc + 4]);
            }
            #pragma unroll
            for (int ni = 0; ni < 4; ni++) {
                int col = wn * 32 + ni * 8 + g;
                b[ni][0] = __float_as_uint(Bs[(kk * 8 + tg)     * 72 + col]);
                b[ni][1] = __float_as_uint(Bs[(kk * 8 + tg + 4) * 72 + col]);
            }
            #pragma unroll
            for (int mi = 0; mi < 2; mi++)
                #pragma unroll
                for (int ni = 0; ni < 4; ni++)
                    asm volatile(
                        "mma.sync.aligned.m16n8k8.row.col.f32.tf32.tf32.f32 "
                        "{%0,%1,%2,%3}, {%4,%5,%6,%7}, {%8,%9}, {%0,%1,%2,%3};"
                        : "+f"(acc[mi][ni][0]), "+f"(acc[mi][ni][1]),
                          "+f"(acc[mi][ni][2]), "+f"(acc[mi][ni][3])
                        : "r"(a[mi][0]), "r"(a[mi][1]), "r"(a[mi][2]), "r"(a[mi][3]),
                          "r"(b[ni][0]), "r"(b[ni][1]));
        }
        __syncthreads();
    }

    #pragma unroll
    for (int mi = 0; mi < 2; mi++) {
        int r = row0 + wm * 32 + mi * 16 + g;
        #pragma unroll
        for (int ni = 0; ni < 4; ni++) {
            int c = col0 + wn * 32 + ni * 8 + tg * 2;
            float bx = bias ? __ldg(bias + c) : 0.f;
            float by = bias ? __ldg(bias + c + 1) : 0.f;
            float v0 = acc[mi][ni][0] + bx, v1 = acc[mi][ni][1] + by;
            float v2 = acc[mi][ni][2] + bx, v3 = acc[mi][ni][3] + by;
            if (Ch) {
                if (r < M)
                    *reinterpret_cast<__half2*>(Ch + (size_t)r * Ncols + c) =
                        __floats2half2_rn(v0, v1);
                if (r + 8 < M)
                    *reinterpret_cast<__half2*>(Ch + (size_t)(r + 8) * Ncols + c) =
                        __floats2half2_rn(v2, v3);
            } else {
                if (r < M)
                    *reinterpret_cast<float2*>(C + (size_t)r * Ncols + c) =
                        make_float2(v0, v1);
                if (r + 8 < M)
                    *reinterpret_cast<float2*>(C + (size_t)(r + 8) * Ncols + c) =
                        make_float2(v2, v3);
            }
        }
    }
}

// ---------------------------------------------------------------------------
// Launch sequence (single stream, graph-capturable: kernels only, 9 launches).
// ---------------------------------------------------------------------------
extern "C" void kernel_launch(void* const* d_in, const int* in_sizes, int n_in,
                              void* d_out, int out_size) {
    const float* features  = (const float*)d_in[0];
    const float* edge_vals = (const float*)d_in[1];
    const float* W1  = (const float*)d_in[2];
    const float* db1 = (const float*)d_in[3];
    // d_in[4] = b1  : cancels in BatchNorm
    const float* g1  = (const float*)d_in[5];
    const float* be1 = (const float*)d_in[6];
    const float* W2  = (const float*)d_in[7];
    // d_in[8] = b2  : cancels in BatchNorm
    const float* g2  = (const float*)d_in[9];
    const float* be2 = (const float*)d_in[10];
    const float* Wf  = (const float*)d_in[11];
    const float* bf  = (const float*)d_in[12];
    const int* erows = (const int*)d_in[13];
    const int* ecols = (const int*)d_in[14];
    const int* idx   = (const int*)d_in[15];
    float* out = (float*)d_out;

    int N = in_sizes[0] / FDIM;   // 50000
    int E = in_sizes[1];          // 800000
    int M = in_sizes[15];         // 25000
    float invN = 1.0f / (float)N;

    float *b1, *su1, *sq1, *su2, *sq2;
    __half *hb;
    cudaGetSymbolAddress((void**)&b1, g_buf1);
    cudaGetSymbolAddress((void**)&hb, g_hbuf);
    cudaGetSymbolAddress((void**)&su1, g_sum1);
    cudaGetSymbolAddress((void**)&sq1, g_sumsq1);
    cudaGetSymbolAddress((void**)&su2, g_sum2);
    cudaGetSymbolAddress((void**)&sq2, g_sumsq2);

    int eblocks = (E + 255) / 256;
    int nb = (N + 1023) / 1024;
    dim3 ggrid(FDIM / 64, (N + 127) / 128);
    int spmm_blocks = (N + 8 * RPW - 1) / (8 * RPW);

    // CSR build (g_cnt is zero on entry; scan1 restores the invariant)
    hist_kernel<<<eblocks, 256>>>(erows, E);
    scan1_kernel<<<nb, 1024>>>(N);
    scan3_kernel<<<nb, 1024>>>(N, E);
    scatter_kernel<<<eblocks, 256>>>(erows, ecols, edge_vals, E);

    // layer 1 (gemm -> fp16, spmm fp16->fp32 + stats into layer-1 buffers)
    gemm_tf32<<<ggrid, 256>>>(features, W1, db1, nullptr,
                              nullptr, nullptr, nullptr, nullptr, 0.f,
                              nullptr, hb, N, FDIM, FDIM);
    spmm_csr<<<spmm_blocks, 256>>>((const uint4*)hb, (float4*)b1, su1, sq1, N);

    // layer 2 (BN1+ReLU computed inline from layer-1 stats; gemm -> fp16)
    gemm_tf32<<<ggrid, 256>>>(b1, W2, nullptr, nullptr,
                              su1, sq1, g1, be1, invN,
                              nullptr, hb, N, FDIM, FDIM);
    spmm_csr<<<spmm_blocks, 256>>>((const uint4*)hb, (float4*)b1, su2, sq2, N);

    // head (BN2+ReLU inline from layer-2 stats + gather; fp32 out)
    gemm_tf32<<<dim3(128 / 64, (M + 127) / 128), 256>>>(
        b1, Wf, bf, idx,
        su2, sq2, g2, be2, invN,
        out, nullptr, M, 128, FDIM);
}